// round 1
// baseline (speedup 1.0000x reference)
#include <cuda_runtime.h>
#include <math.h>

#define T_TOK 1024
#define H_DIM 1024
#define E_NUM 32
#define I_DIM 512
#define IS_DIM 2048
#define NGROUP 8
#define GSIZE 4
#define TOPKG 4
#define TOPK 8
#define RSCALE 2.5f

#define BM 64
#define BN 64
#define BK 16

// Scratch (static device globals; no runtime allocation)
__device__ float g_act[(size_t)E_NUM * T_TOK * I_DIM];   // routed activations (slot-compacted per expert)
__device__ float g_sact[(size_t)T_TOK * IS_DIM];         // shared-expert activations
__device__ int   g_cnt[E_NUM];
__device__ int   g_tok[E_NUM * T_TOK];
__device__ float g_wgt[E_NUM * T_TOK];

__global__ void k_zero_cnt() {
    if (threadIdx.x < E_NUM) g_cnt[threadIdx.x] = 0;
}

__device__ __forceinline__ float silu_f(float v) { return v / (1.f + expf(-v)); }

// ---------------------------------------------------------------------------
// Gate GEMV + DeepseekV3 noaux_tc routing + per-expert gather
// one block per token, 8 warps each handle 4 experts' dot products
// ---------------------------------------------------------------------------
__global__ __launch_bounds__(256) void k_gate_route(
    const float* __restrict__ x,
    const float* __restrict__ gate_w,
    const float* __restrict__ e_bias)
{
    __shared__ float s_logit[E_NUM];
    const int t = blockIdx.x;
    const int warp = threadIdx.x >> 5, lane = threadIdx.x & 31;
    const float* xr = x + (size_t)t * H_DIM;
    for (int e = warp; e < E_NUM; e += 8) {
        const float* gw = gate_w + (size_t)e * H_DIM;
        float s = 0.f;
        for (int k = lane; k < H_DIM; k += 32) s += xr[k] * gw[k];
        #pragma unroll
        for (int o = 16; o; o >>= 1) s += __shfl_xor_sync(0xffffffffu, s, o);
        if (lane == 0) s_logit[e] = s;
    }
    __syncthreads();
    if (threadIdx.x != 0) return;

    float scores[E_NUM], swb[E_NUM];
    for (int e = 0; e < E_NUM; e++) {
        float sc = 1.f / (1.f + expf(-s_logit[e]));
        scores[e] = sc;
        swb[e] = sc + e_bias[e];
    }
    // group scores = sum of top-2 per group of 4
    float gs[NGROUP];
    for (int g = 0; g < NGROUP; g++) {
        float m1 = -1e30f, m2 = -1e30f;
        for (int j = 0; j < GSIZE; j++) {
            float v = swb[g * GSIZE + j];
            if (v > m1) { m2 = m1; m1 = v; }
            else if (v > m2) m2 = v;
        }
        gs[g] = m1 + m2;
    }
    // top-4 groups (strict > => lowest index wins ties, matching jax top_k)
    bool gsel[NGROUP] = {false};
    for (int it = 0; it < TOPKG; it++) {
        int bi = 0; float bv = -1e30f;
        for (int g = 0; g < NGROUP; g++)
            if (!gsel[g] && gs[g] > bv) { bv = gs[g]; bi = g; }
        gsel[bi] = true;
    }
    // top-8 experts among masked swb
    float val[E_NUM];
    for (int e = 0; e < E_NUM; e++) val[e] = gsel[e / GSIZE] ? swb[e] : 0.f;
    bool taken[E_NUM] = {false};
    int sel[TOPK];
    float denom = 0.f;
    for (int it = 0; it < TOPK; it++) {
        int bi = 0; float bv = -1e30f;
        for (int e = 0; e < E_NUM; e++)
            if (!taken[e] && val[e] > bv) { bv = val[e]; bi = e; }
        taken[bi] = true; sel[it] = bi; denom += scores[bi];
    }
    float inv = RSCALE / (denom + 1e-20f);
    for (int it = 0; it < TOPK; it++) {
        int e = sel[it];
        int slot = atomicAdd(&g_cnt[e], 1);
        g_tok[e * T_TOK + slot] = t;
        g_wgt[e * T_TOK + slot] = scores[e] * inv;
    }
}

// ---------------------------------------------------------------------------
// Dual GEMM (gate & up) + silu*up (* combine weight) epilogue
// ROUTED: rows gathered by g_tok for expert blockIdx.z, output to g_act
// !ROUTED: identity rows (shared expert), output to g_sact
// C tile 64x64, 256 threads, 4x4 per thread, K-chunks of 16
// ---------------------------------------------------------------------------
template<bool ROUTED>
__global__ __launch_bounds__(256)
void k_dual_silu(const float* __restrict__ X,
                 const float* __restrict__ Wg0,
                 const float* __restrict__ Wu0,
                 int N, int K)
{
    const int e = ROUTED ? blockIdx.z : 0;
    const int M = ROUTED ? g_cnt[e] : T_TOK;
    const int m0 = blockIdx.y * BM;
    if (m0 >= M) return;
    const int n0 = blockIdx.x * BN;
    const float* __restrict__ Wg = Wg0 + (size_t)e * K * N;
    const float* __restrict__ Wu = Wu0 + (size_t)e * K * N;
    float* __restrict__ Act = ROUTED ? (g_act + (size_t)e * T_TOK * I_DIM) : g_sact;

    __shared__ float As[BK][BM + 4];
    __shared__ float Bgs[BK][BN];
    __shared__ float Bus[BK][BN];

    const int tid = threadIdx.x;
    const int a_row = tid >> 2;
    const int a_k   = (tid & 3) << 2;
    const int gm = m0 + a_row;
    const bool a_ok = gm < M;
    int srow = 0;
    if (a_ok) srow = ROUTED ? g_tok[e * T_TOK + gm] : gm;
    const float* a_ptr = X + (size_t)srow * K + a_k;

    const int b_k = tid >> 4;
    const int b_n = (tid & 15) << 2;
    const float* bg_ptr = Wg + (size_t)b_k * N + n0 + b_n;
    const float* bu_ptr = Wu + (size_t)b_k * N + n0 + b_n;

    const int tx = tid & 15, ty = tid >> 4;

    float ag[4][4], au[4][4];
    #pragma unroll
    for (int i = 0; i < 4; i++)
        #pragma unroll
        for (int j = 0; j < 4; j++) { ag[i][j] = 0.f; au[i][j] = 0.f; }

    for (int k0 = 0; k0 < K; k0 += BK) {
        float4 av = a_ok ? *(const float4*)(a_ptr + k0)
                         : make_float4(0.f, 0.f, 0.f, 0.f);
        float4 bgv = *(const float4*)(bg_ptr + (size_t)k0 * N);
        float4 buv = *(const float4*)(bu_ptr + (size_t)k0 * N);
        As[a_k + 0][a_row] = av.x;
        As[a_k + 1][a_row] = av.y;
        As[a_k + 2][a_row] = av.z;
        As[a_k + 3][a_row] = av.w;
        *(float4*)&Bgs[b_k][b_n] = bgv;
        *(float4*)&Bus[b_k][b_n] = buv;
        __syncthreads();
        #pragma unroll
        for (int k = 0; k < BK; k++) {
            float4 a4 = *(const float4*)&As[k][ty << 2];
            float4 g4 = *(const float4*)&Bgs[k][tx << 2];
            float4 u4 = *(const float4*)&Bus[k][tx << 2];
            float aa[4] = {a4.x, a4.y, a4.z, a4.w};
            float gg[4] = {g4.x, g4.y, g4.z, g4.w};
            float uu[4] = {u4.x, u4.y, u4.z, u4.w};
            #pragma unroll
            for (int i = 0; i < 4; i++)
                #pragma unroll
                for (int j = 0; j < 4; j++) {
                    ag[i][j] += aa[i] * gg[j];
                    au[i][j] += aa[i] * uu[j];
                }
        }
        __syncthreads();
    }

    #pragma unroll
    for (int i = 0; i < 4; i++) {
        int rm = m0 + (ty << 2) + i;
        if (rm >= M) break;
        float sc = ROUTED ? g_wgt[e * T_TOK + rm] : 1.f;
        float4 o;
        o.x = silu_f(ag[i][0]) * au[i][0] * sc;
        o.y = silu_f(ag[i][1]) * au[i][1] * sc;
        o.z = silu_f(ag[i][2]) * au[i][2] * sc;
        o.w = silu_f(ag[i][3]) * au[i][3] * sc;
        *(float4*)(Act + (size_t)rm * N + n0 + (tx << 2)) = o;
    }
}

// ---------------------------------------------------------------------------
// Down projection. ROUTED: act[slot] @ w_down[e], atomicAdd-scatter to out[token]
// !ROUTED: g_sact @ ws_down, plain store (runs first, covers every element)
// ---------------------------------------------------------------------------
template<bool ROUTED>
__global__ __launch_bounds__(256)
void k_down(const float* __restrict__ Bd0,
            float* __restrict__ Out,
            int N, int K)
{
    const int e = ROUTED ? blockIdx.z : 0;
    const int M = ROUTED ? g_cnt[e] : T_TOK;
    const int m0 = blockIdx.y * BM;
    if (m0 >= M) return;
    const int n0 = blockIdx.x * BN;
    const float* __restrict__ A = ROUTED ? (g_act + (size_t)e * T_TOK * K) : g_sact;
    const float* __restrict__ B = Bd0 + (size_t)e * K * N;

    __shared__ float As[BK][BM + 4];
    __shared__ float Bs[BK][BN];

    const int tid = threadIdx.x;
    const int a_row = tid >> 2;
    const int a_k   = (tid & 3) << 2;
    const bool a_ok = (m0 + a_row) < M;
    const float* a_ptr = A + (size_t)(m0 + a_row) * K + a_k;

    const int b_k = tid >> 4;
    const int b_n = (tid & 15) << 2;
    const float* b_ptr = B + (size_t)b_k * N + n0 + b_n;

    const int tx = tid & 15, ty = tid >> 4;

    float acc[4][4];
    #pragma unroll
    for (int i = 0; i < 4; i++)
        #pragma unroll
        for (int j = 0; j < 4; j++) acc[i][j] = 0.f;

    for (int k0 = 0; k0 < K; k0 += BK) {
        float4 av = a_ok ? *(const float4*)(a_ptr + k0)
                         : make_float4(0.f, 0.f, 0.f, 0.f);
        float4 bv = *(const float4*)(b_ptr + (size_t)k0 * N);
        As[a_k + 0][a_row] = av.x;
        As[a_k + 1][a_row] = av.y;
        As[a_k + 2][a_row] = av.z;
        As[a_k + 3][a_row] = av.w;
        *(float4*)&Bs[b_k][b_n] = bv;
        __syncthreads();
        #pragma unroll
        for (int k = 0; k < BK; k++) {
            float4 a4 = *(const float4*)&As[k][ty << 2];
            float4 b4 = *(const float4*)&Bs[k][tx << 2];
            float aa[4] = {a4.x, a4.y, a4.z, a4.w};
            float bb[4] = {b4.x, b4.y, b4.z, b4.w};
            #pragma unroll
            for (int i = 0; i < 4; i++)
                #pragma unroll
                for (int j = 0; j < 4; j++)
                    acc[i][j] += aa[i] * bb[j];
        }
        __syncthreads();
    }

    #pragma unroll
    for (int i = 0; i < 4; i++) {
        int rm = m0 + (ty << 2) + i;
        if (rm >= M) break;
        int tok = ROUTED ? g_tok[e * T_TOK + rm] : rm;
        float* dst = Out + (size_t)tok * N + n0 + (tx << 2);
        if (ROUTED) {
            atomicAdd(dst + 0, acc[i][0]);
            atomicAdd(dst + 1, acc[i][1]);
            atomicAdd(dst + 2, acc[i][2]);
            atomicAdd(dst + 3, acc[i][3]);
        } else {
            float4 o = make_float4(acc[i][0], acc[i][1], acc[i][2], acc[i][3]);
            *(float4*)dst = o;
        }
    }
}

// ---------------------------------------------------------------------------
extern "C" void kernel_launch(void* const* d_in, const int* in_sizes, int n_in,
                              void* d_out, int out_size)
{
    const float* x       = (const float*)d_in[0];
    const float* gate_w  = (const float*)d_in[1];
    const float* e_bias  = (const float*)d_in[2];
    const float* w_gate  = (const float*)d_in[3];
    const float* w_up    = (const float*)d_in[4];
    const float* w_down  = (const float*)d_in[5];
    const float* ws_gate = (const float*)d_in[6];
    const float* ws_up   = (const float*)d_in[7];
    const float* ws_down = (const float*)d_in[8];
    float* out = (float*)d_out;

    k_zero_cnt<<<1, 32>>>();
    k_gate_route<<<T_TOK, 256>>>(x, gate_w, e_bias);
    // shared expert: act then down (down stores directly -> initializes out)
    k_dual_silu<false><<<dim3(IS_DIM / BN, T_TOK / BM, 1), 256>>>(x, ws_gate, ws_up, IS_DIM, H_DIM);
    k_down<false><<<dim3(H_DIM / BN, T_TOK / BM, 1), 256>>>(ws_down, out, H_DIM, IS_DIM);
    // routed experts: act (gathered, weighted) then down (atomicAdd scatter)
    k_dual_silu<true><<<dim3(I_DIM / BN, T_TOK / BM, E_NUM), 256>>>(x, w_gate, w_up, I_DIM, H_DIM);
    k_down<true><<<dim3(H_DIM / BN, T_TOK / BM, E_NUM), 256>>>(w_down, out, H_DIM, I_DIM);
}

// round 2
// speedup vs baseline: 1.8727x; 1.8727x over previous
#include <cuda_runtime.h>
#include <math.h>
#include <stdint.h>

#define T_TOK 1024
#define H_DIM 1024
#define E_NUM 32
#define I_DIM 512
#define IS_DIM 2048
#define NGROUP 8
#define GSIZE 4
#define TOPKG 4
#define TOPK 8
#define RSCALE 2.5f

// Scratch (static device globals; no runtime allocation)
__device__ float g_act[(size_t)E_NUM * T_TOK * I_DIM];   // routed activations (slot-compacted per expert)
__device__ float g_sact[(size_t)T_TOK * IS_DIM];         // shared-expert activations
__device__ int   g_cnt[E_NUM];
__device__ int   g_tok[E_NUM * T_TOK];
__device__ float g_wgt[E_NUM * T_TOK];

__global__ void k_zero_cnt() {
    if (threadIdx.x < E_NUM) g_cnt[threadIdx.x] = 0;
}

__device__ __forceinline__ float silu_f(float v) { return v / (1.f + expf(-v)); }

__device__ __forceinline__ uint32_t f2tf(float f) {
    uint32_t u;
    asm("cvt.rna.tf32.f32 %0, %1;" : "=r"(u) : "f"(f));
    return u;
}

__device__ __forceinline__ void mma_tf32(float* c,
                                         uint32_t a0, uint32_t a1, uint32_t a2, uint32_t a3,
                                         uint32_t b0, uint32_t b1)
{
    asm volatile(
        "mma.sync.aligned.m16n8k8.row.col.f32.tf32.tf32.f32 "
        "{%0,%1,%2,%3}, {%4,%5,%6,%7}, {%8,%9}, {%0,%1,%2,%3};\n"
        : "+f"(c[0]), "+f"(c[1]), "+f"(c[2]), "+f"(c[3])
        : "r"(a0), "r"(a1), "r"(a2), "r"(a3), "r"(b0), "r"(b1));
}

// ---------------------------------------------------------------------------
// Gate GEMV + DeepseekV3 noaux_tc routing + per-expert gather
// ---------------------------------------------------------------------------
__global__ __launch_bounds__(256) void k_gate_route(
    const float* __restrict__ x,
    const float* __restrict__ gate_w,
    const float* __restrict__ e_bias)
{
    __shared__ float s_logit[E_NUM];
    const int t = blockIdx.x;
    const int warp = threadIdx.x >> 5, lane = threadIdx.x & 31;
    const float* xr = x + (size_t)t * H_DIM;
    for (int e = warp; e < E_NUM; e += 8) {
        const float* gw = gate_w + (size_t)e * H_DIM;
        float s = 0.f;
        for (int k = lane; k < H_DIM; k += 32) s += xr[k] * gw[k];
        #pragma unroll
        for (int o = 16; o; o >>= 1) s += __shfl_xor_sync(0xffffffffu, s, o);
        if (lane == 0) s_logit[e] = s;
    }
    __syncthreads();
    if (threadIdx.x != 0) return;

    float scores[E_NUM], swb[E_NUM];
    for (int e = 0; e < E_NUM; e++) {
        float sc = 1.f / (1.f + expf(-s_logit[e]));
        scores[e] = sc;
        swb[e] = sc + e_bias[e];
    }
    float gs[NGROUP];
    for (int g = 0; g < NGROUP; g++) {
        float m1 = -1e30f, m2 = -1e30f;
        for (int j = 0; j < GSIZE; j++) {
            float v = swb[g * GSIZE + j];
            if (v > m1) { m2 = m1; m1 = v; }
            else if (v > m2) m2 = v;
        }
        gs[g] = m1 + m2;
    }
    bool gsel[NGROUP] = {false};
    for (int it = 0; it < TOPKG; it++) {
        int bi = 0; float bv = -1e30f;
        for (int g = 0; g < NGROUP; g++)
            if (!gsel[g] && gs[g] > bv) { bv = gs[g]; bi = g; }
        gsel[bi] = true;
    }
    float val[E_NUM];
    for (int e = 0; e < E_NUM; e++) val[e] = gsel[e / GSIZE] ? swb[e] : 0.f;
    bool taken[E_NUM] = {false};
    int sel[TOPK];
    float denom = 0.f;
    for (int it = 0; it < TOPK; it++) {
        int bi = 0; float bv = -1e30f;
        for (int e = 0; e < E_NUM; e++)
            if (!taken[e] && val[e] > bv) { bv = val[e]; bi = e; }
        taken[bi] = true; sel[it] = bi; denom += scores[bi];
    }
    float inv = RSCALE / (denom + 1e-20f);
    for (int it = 0; it < TOPK; it++) {
        int e = sel[it];
        int slot = atomicAdd(&g_cnt[e], 1);
        g_tok[e * T_TOK + slot] = t;
        g_wgt[e * T_TOK + slot] = scores[e] * inv;
    }
}

// ---------------------------------------------------------------------------
// Dual tf32 MMA GEMM: act = silu(X@Wg) * (X@Wu) [* combine weight]
// Block tile 128(M) x 64(N), BK=32, 8 warps (4m x 2n), warp tile 32x32
// ---------------------------------------------------------------------------
template<bool ROUTED>
__global__ __launch_bounds__(256, 2)
void k_dual_mma(const float* __restrict__ X,
                const float* __restrict__ Wg0,
                const float* __restrict__ Wu0,
                int N, int K)
{
    const int e = ROUTED ? blockIdx.z : 0;
    const int M = ROUTED ? g_cnt[e] : T_TOK;
    const int m0 = blockIdx.y * 128;
    if (m0 >= M) return;
    const int n0 = blockIdx.x * 64;
    const float* __restrict__ Wg = Wg0 + (size_t)e * K * N;
    const float* __restrict__ Wu = Wu0 + (size_t)e * K * N;
    float* __restrict__ Act = ROUTED ? (g_act + (size_t)e * T_TOK * I_DIM) : g_sact;

    __shared__ uint32_t As[32][132];
    __shared__ uint32_t Bgs[32][68];
    __shared__ uint32_t Bus[32][68];

    const int tid = threadIdx.x;
    const int warp = tid >> 5, lane = tid & 31;
    const int wm = warp & 3, wn = warp >> 2;
    const int grp = lane >> 2, tg = lane & 3;

    // A gmem mapping: 128 rows x 32 cols = 1024 float4, 4 per thread
    const float* aptr[4];
    bool aok[4];
    #pragma unroll
    for (int i = 0; i < 4; i++) {
        int idx = tid + i * 256;
        int r = idx >> 3, c4 = (idx & 7) << 2;
        int gm = m0 + r;
        bool ok = gm < M;
        int srow = 0;
        if (ok) srow = ROUTED ? g_tok[e * T_TOK + gm] : gm;
        aptr[i] = X + (size_t)srow * K + c4;
        aok[i] = ok;
    }
    // B gmem mapping: 32 rows x 64 cols = 512 float4, 2 per thread (each matrix)
    const float* gptr[2];
    const float* uptr[2];
    #pragma unroll
    for (int i = 0; i < 2; i++) {
        int idx = tid + i * 256;
        int r = idx >> 4, c4 = (idx & 15) << 2;
        gptr[i] = Wg + (size_t)r * N + n0 + c4;
        uptr[i] = Wu + (size_t)r * N + n0 + c4;
    }

    float4 rA[4], rG[2], rU[2];
    // prologue: load k0 = 0
    #pragma unroll
    for (int i = 0; i < 4; i++)
        rA[i] = aok[i] ? *(const float4*)(aptr[i]) : make_float4(0.f, 0.f, 0.f, 0.f);
    #pragma unroll
    for (int i = 0; i < 2; i++) {
        rG[i] = *(const float4*)(gptr[i]);
        rU[i] = *(const float4*)(uptr[i]);
    }
    // store to smem
    #pragma unroll
    for (int i = 0; i < 4; i++) {
        int idx = tid + i * 256;
        int r = idx >> 3, c4 = (idx & 7) << 2;
        As[c4 + 0][r] = f2tf(rA[i].x);
        As[c4 + 1][r] = f2tf(rA[i].y);
        As[c4 + 2][r] = f2tf(rA[i].z);
        As[c4 + 3][r] = f2tf(rA[i].w);
    }
    #pragma unroll
    for (int i = 0; i < 2; i++) {
        int idx = tid + i * 256;
        int r = idx >> 4, c4 = (idx & 15) << 2;
        Bgs[r][c4 + 0] = f2tf(rG[i].x);
        Bgs[r][c4 + 1] = f2tf(rG[i].y);
        Bgs[r][c4 + 2] = f2tf(rG[i].z);
        Bgs[r][c4 + 3] = f2tf(rG[i].w);
        Bus[r][c4 + 0] = f2tf(rU[i].x);
        Bus[r][c4 + 1] = f2tf(rU[i].y);
        Bus[r][c4 + 2] = f2tf(rU[i].z);
        Bus[r][c4 + 3] = f2tf(rU[i].w);
    }
    __syncthreads();

    float cg[2][4][4], cu[2][4][4];
    #pragma unroll
    for (int mi = 0; mi < 2; mi++)
        #pragma unroll
        for (int ni = 0; ni < 4; ni++)
            #pragma unroll
            for (int q = 0; q < 4; q++) { cg[mi][ni][q] = 0.f; cu[mi][ni][q] = 0.f; }

    for (int k0 = 0; k0 < K; k0 += 32) {
        bool more = (k0 + 32) < K;
        if (more) {
            #pragma unroll
            for (int i = 0; i < 4; i++)
                rA[i] = aok[i] ? *(const float4*)(aptr[i] + k0 + 32) : make_float4(0.f, 0.f, 0.f, 0.f);
            #pragma unroll
            for (int i = 0; i < 2; i++) {
                rG[i] = *(const float4*)(gptr[i] + (size_t)(k0 + 32) * N);
                rU[i] = *(const float4*)(uptr[i] + (size_t)(k0 + 32) * N);
            }
        }
        #pragma unroll
        for (int ks = 0; ks < 4; ks++) {
            const int kb = ks * 8;
            uint32_t af[2][4];
            #pragma unroll
            for (int mi = 0; mi < 2; mi++) {
                int m = wm * 32 + mi * 16 + grp;
                af[mi][0] = As[kb + tg][m];
                af[mi][1] = As[kb + tg][m + 8];
                af[mi][2] = As[kb + tg + 4][m];
                af[mi][3] = As[kb + tg + 4][m + 8];
            }
            #pragma unroll
            for (int ni = 0; ni < 4; ni++) {
                int n = wn * 32 + ni * 8 + grp;
                uint32_t bg0 = Bgs[kb + tg][n];
                uint32_t bg1 = Bgs[kb + tg + 4][n];
                uint32_t bu0 = Bus[kb + tg][n];
                uint32_t bu1 = Bus[kb + tg + 4][n];
                #pragma unroll
                for (int mi = 0; mi < 2; mi++) {
                    mma_tf32(cg[mi][ni], af[mi][0], af[mi][1], af[mi][2], af[mi][3], bg0, bg1);
                    mma_tf32(cu[mi][ni], af[mi][0], af[mi][1], af[mi][2], af[mi][3], bu0, bu1);
                }
            }
        }
        __syncthreads();
        if (more) {
            #pragma unroll
            for (int i = 0; i < 4; i++) {
                int idx = tid + i * 256;
                int r = idx >> 3, c4 = (idx & 7) << 2;
                As[c4 + 0][r] = f2tf(rA[i].x);
                As[c4 + 1][r] = f2tf(rA[i].y);
                As[c4 + 2][r] = f2tf(rA[i].z);
                As[c4 + 3][r] = f2tf(rA[i].w);
            }
            #pragma unroll
            for (int i = 0; i < 2; i++) {
                int idx = tid + i * 256;
                int r = idx >> 4, c4 = (idx & 15) << 2;
                Bgs[r][c4 + 0] = f2tf(rG[i].x);
                Bgs[r][c4 + 1] = f2tf(rG[i].y);
                Bgs[r][c4 + 2] = f2tf(rG[i].z);
                Bgs[r][c4 + 3] = f2tf(rG[i].w);
                Bus[r][c4 + 0] = f2tf(rU[i].x);
                Bus[r][c4 + 1] = f2tf(rU[i].y);
                Bus[r][c4 + 2] = f2tf(rU[i].z);
                Bus[r][c4 + 3] = f2tf(rU[i].w);
            }
            __syncthreads();
        }
    }

    // epilogue: silu(g)*u (* wgt)
    #pragma unroll
    for (int mi = 0; mi < 2; mi++) {
        int r0 = m0 + wm * 32 + mi * 16 + grp;
        int r1 = r0 + 8;
        float w0 = 1.f, w1 = 1.f;
        if (ROUTED) {
            if (r0 < M) w0 = g_wgt[e * T_TOK + r0];
            if (r1 < M) w1 = g_wgt[e * T_TOK + r1];
        }
        #pragma unroll
        for (int ni = 0; ni < 4; ni++) {
            int col = n0 + wn * 32 + ni * 8 + tg * 2;
            if (r0 < M) {
                float2 v;
                v.x = silu_f(cg[mi][ni][0]) * cu[mi][ni][0] * w0;
                v.y = silu_f(cg[mi][ni][1]) * cu[mi][ni][1] * w0;
                *(float2*)(Act + (size_t)r0 * N + col) = v;
            }
            if (r1 < M) {
                float2 v;
                v.x = silu_f(cg[mi][ni][2]) * cu[mi][ni][2] * w1;
                v.y = silu_f(cg[mi][ni][3]) * cu[mi][ni][3] * w1;
                *(float2*)(Act + (size_t)r1 * N + col) = v;
            }
        }
    }
}

// ---------------------------------------------------------------------------
// Down-proj tf32 MMA GEMM. Block 128x128, BK=32, 8 warps (2m x 4n), warp 64x32
// ROUTED: atomicAdd-scatter to out[token]; else plain store
// ---------------------------------------------------------------------------
template<bool ROUTED>
__global__ __launch_bounds__(256, 2)
void k_down_mma(const float* __restrict__ Bd0,
                float* __restrict__ Out,
                int N, int K)
{
    const int e = ROUTED ? blockIdx.z : 0;
    const int M = ROUTED ? g_cnt[e] : T_TOK;
    const int m0 = blockIdx.y * 128;
    if (m0 >= M) return;
    const int n0 = blockIdx.x * 128;
    const float* __restrict__ A = ROUTED ? (g_act + (size_t)e * T_TOK * K) : g_sact;
    const float* __restrict__ B = Bd0 + (size_t)e * K * N;

    __shared__ uint32_t As[32][132];
    __shared__ uint32_t Bs[32][132];

    const int tid = threadIdx.x;
    const int warp = tid >> 5, lane = tid & 31;
    const int wm = warp & 1, wn = warp >> 1;
    const int grp = lane >> 2, tg = lane & 3;

    const float* aptr[4];
    bool aok[4];
    #pragma unroll
    for (int i = 0; i < 4; i++) {
        int idx = tid + i * 256;
        int r = idx >> 3, c4 = (idx & 7) << 2;
        bool ok = (m0 + r) < M;
        aptr[i] = A + (size_t)(ok ? (m0 + r) : 0) * K + c4;
        aok[i] = ok;
    }
    const float* bptr[4];
    #pragma unroll
    for (int i = 0; i < 4; i++) {
        int idx = tid + i * 256;
        int r = idx >> 5, c4 = (idx & 31) << 2;
        bptr[i] = B + (size_t)r * N + n0 + c4;
    }

    float4 rA[4], rB[4];
    #pragma unroll
    for (int i = 0; i < 4; i++) {
        rA[i] = aok[i] ? *(const float4*)(aptr[i]) : make_float4(0.f, 0.f, 0.f, 0.f);
        rB[i] = *(const float4*)(bptr[i]);
    }
    #pragma unroll
    for (int i = 0; i < 4; i++) {
        int idx = tid + i * 256;
        int ar = idx >> 3, ac4 = (idx & 7) << 2;
        As[ac4 + 0][ar] = f2tf(rA[i].x);
        As[ac4 + 1][ar] = f2tf(rA[i].y);
        As[ac4 + 2][ar] = f2tf(rA[i].z);
        As[ac4 + 3][ar] = f2tf(rA[i].w);
        int br = idx >> 5, bc4 = (idx & 31) << 2;
        Bs[br][bc4 + 0] = f2tf(rB[i].x);
        Bs[br][bc4 + 1] = f2tf(rB[i].y);
        Bs[br][bc4 + 2] = f2tf(rB[i].z);
        Bs[br][bc4 + 3] = f2tf(rB[i].w);
    }
    __syncthreads();

    float acc[4][4][4];
    #pragma unroll
    for (int mi = 0; mi < 4; mi++)
        #pragma unroll
        for (int ni = 0; ni < 4; ni++)
            #pragma unroll
            for (int q = 0; q < 4; q++) acc[mi][ni][q] = 0.f;

    for (int k0 = 0; k0 < K; k0 += 32) {
        bool more = (k0 + 32) < K;
        if (more) {
            #pragma unroll
            for (int i = 0; i < 4; i++) {
                rA[i] = aok[i] ? *(const float4*)(aptr[i] + k0 + 32) : make_float4(0.f, 0.f, 0.f, 0.f);
                rB[i] = *(const float4*)(bptr[i] + (size_t)(k0 + 32) * N);
            }
        }
        #pragma unroll
        for (int ks = 0; ks < 4; ks++) {
            const int kb = ks * 8;
            uint32_t af[4][4];
            #pragma unroll
            for (int mi = 0; mi < 4; mi++) {
                int m = wm * 64 + mi * 16 + grp;
                af[mi][0] = As[kb + tg][m];
                af[mi][1] = As[kb + tg][m + 8];
                af[mi][2] = As[kb + tg + 4][m];
                af[mi][3] = As[kb + tg + 4][m + 8];
            }
            #pragma unroll
            for (int ni = 0; ni < 4; ni++) {
                int n = wn * 32 + ni * 8 + grp;
                uint32_t b0 = Bs[kb + tg][n];
                uint32_t b1 = Bs[kb + tg + 4][n];
                #pragma unroll
                for (int mi = 0; mi < 4; mi++)
                    mma_tf32(acc[mi][ni], af[mi][0], af[mi][1], af[mi][2], af[mi][3], b0, b1);
            }
        }
        __syncthreads();
        if (more) {
            #pragma unroll
            for (int i = 0; i < 4; i++) {
                int idx = tid + i * 256;
                int ar = idx >> 3, ac4 = (idx & 7) << 2;
                As[ac4 + 0][ar] = f2tf(rA[i].x);
                As[ac4 + 1][ar] = f2tf(rA[i].y);
                As[ac4 + 2][ar] = f2tf(rA[i].z);
                As[ac4 + 3][ar] = f2tf(rA[i].w);
                int br = idx >> 5, bc4 = (idx & 31) << 2;
                Bs[br][bc4 + 0] = f2tf(rB[i].x);
                Bs[br][bc4 + 1] = f2tf(rB[i].y);
                Bs[br][bc4 + 2] = f2tf(rB[i].z);
                Bs[br][bc4 + 3] = f2tf(rB[i].w);
            }
            __syncthreads();
        }
    }

    #pragma unroll
    for (int mi = 0; mi < 4; mi++) {
        int r0 = m0 + wm * 64 + mi * 16 + grp;
        int r1 = r0 + 8;
        int tok0 = 0, tok1 = 0;
        if (ROUTED) {
            if (r0 < M) tok0 = g_tok[e * T_TOK + r0];
            if (r1 < M) tok1 = g_tok[e * T_TOK + r1];
        } else { tok0 = r0; tok1 = r1; }
        #pragma unroll
        for (int ni = 0; ni < 4; ni++) {
            int col = n0 + wn * 32 + ni * 8 + tg * 2;
            if (ROUTED) {
                if (r0 < M) {
                    atomicAdd(Out + (size_t)tok0 * N + col,     acc[mi][ni][0]);
                    atomicAdd(Out + (size_t)tok0 * N + col + 1, acc[mi][ni][1]);
                }
                if (r1 < M) {
                    atomicAdd(Out + (size_t)tok1 * N + col,     acc[mi][ni][2]);
                    atomicAdd(Out + (size_t)tok1 * N + col + 1, acc[mi][ni][3]);
                }
            } else {
                if (r0 < M) {
                    float2 v = make_float2(acc[mi][ni][0], acc[mi][ni][1]);
                    *(float2*)(Out + (size_t)tok0 * N + col) = v;
                }
                if (r1 < M) {
                    float2 v = make_float2(acc[mi][ni][2], acc[mi][ni][3]);
                    *(float2*)(Out + (size_t)tok1 * N + col) = v;
                }
            }
        }
    }
}

// ---------------------------------------------------------------------------
extern "C" void kernel_launch(void* const* d_in, const int* in_sizes, int n_in,
                              void* d_out, int out_size)
{
    const float* x       = (const float*)d_in[0];
    const float* gate_w  = (const float*)d_in[1];
    const float* e_bias  = (const float*)d_in[2];
    const float* w_gate  = (const float*)d_in[3];
    const float* w_up    = (const float*)d_in[4];
    const float* w_down  = (const float*)d_in[5];
    const float* ws_gate = (const float*)d_in[6];
    const float* ws_up   = (const float*)d_in[7];
    const float* ws_down = (const float*)d_in[8];
    float* out = (float*)d_out;

    k_zero_cnt<<<1, 32>>>();
    k_gate_route<<<T_TOK, 256>>>(x, gate_w, e_bias);
    // shared expert
    k_dual_mma<false><<<dim3(IS_DIM / 64, T_TOK / 128, 1), 256>>>(x, ws_gate, ws_up, IS_DIM, H_DIM);
    k_down_mma<false><<<dim3(H_DIM / 128, T_TOK / 128, 1), 256>>>(ws_down, out, H_DIM, IS_DIM);
    // routed experts
    k_dual_mma<true><<<dim3(I_DIM / 64, T_TOK / 128, E_NUM), 256>>>(x, w_gate, w_up, I_DIM, H_DIM);
    k_down_mma<true><<<dim3(H_DIM / 128, T_TOK / 128, E_NUM), 256>>>(w_down, out, H_DIM, I_DIM);
}

// round 3
// speedup vs baseline: 2.6744x; 1.4281x over previous
#include <cuda_runtime.h>
#include <math.h>
#include <stdint.h>

#define T_TOK 1024
#define H_DIM 1024
#define E_NUM 32
#define I_DIM 512
#define IS_DIM 2048
#define NGROUP 8
#define GSIZE 4
#define TOPKG 4
#define TOPK 8
#define RSCALE 2.5f

// Scratch
__device__ float g_act[(size_t)E_NUM * T_TOK * I_DIM];
__device__ float g_sact[(size_t)T_TOK * IS_DIM];
__device__ int   g_cnt[E_NUM];
__device__ int   g_tok[E_NUM * T_TOK];
__device__ float g_wgt[E_NUM * T_TOK];

__device__ __forceinline__ float silu_f(float v) { return v / (1.f + expf(-v)); }

__device__ __forceinline__ uint32_t f2tf(float f) {
    uint32_t u;
    asm("cvt.rna.tf32.f32 %0, %1;" : "=r"(u) : "f"(f));
    return u;
}

__device__ __forceinline__ void mma_tf32(float* c,
                                         uint32_t a0, uint32_t a1, uint32_t a2, uint32_t a3,
                                         uint32_t b0, uint32_t b1)
{
    asm volatile(
        "mma.sync.aligned.m16n8k8.row.col.f32.tf32.tf32.f32 "
        "{%0,%1,%2,%3}, {%4,%5,%6,%7}, {%8,%9}, {%0,%1,%2,%3};\n"
        : "+f"(c[0]), "+f"(c[1]), "+f"(c[2]), "+f"(c[3])
        : "r"(a0), "r"(a1), "r"(a2), "r"(a3), "r"(b0), "r"(b1));
}

// init: zero expert counters + zero output (for atomicAdd accumulation)
__global__ void k_init(float* __restrict__ out) {
    if (blockIdx.x == 0 && threadIdx.x < E_NUM) g_cnt[threadIdx.x] = 0;
    size_t i = (size_t)blockIdx.x * 256 + threadIdx.x;
    ((float4*)out)[i] = make_float4(0.f, 0.f, 0.f, 0.f);
}

// ---------------------------------------------------------------------------
// Gate GEMV + DeepseekV3 noaux_tc routing + per-expert gather
// ---------------------------------------------------------------------------
__global__ __launch_bounds__(256) void k_gate_route(
    const float* __restrict__ x,
    const float* __restrict__ gate_w,
    const float* __restrict__ e_bias)
{
    __shared__ float s_logit[E_NUM];
    const int t = blockIdx.x;
    const int warp = threadIdx.x >> 5, lane = threadIdx.x & 31;
    const float* xr = x + (size_t)t * H_DIM;
    for (int e = warp; e < E_NUM; e += 8) {
        const float* gw = gate_w + (size_t)e * H_DIM;
        float s = 0.f;
        for (int k = lane; k < H_DIM; k += 32) s += xr[k] * gw[k];
        #pragma unroll
        for (int o = 16; o; o >>= 1) s += __shfl_xor_sync(0xffffffffu, s, o);
        if (lane == 0) s_logit[e] = s;
    }
    __syncthreads();
    if (threadIdx.x != 0) return;

    float scores[E_NUM], swb[E_NUM];
    for (int e = 0; e < E_NUM; e++) {
        float sc = 1.f / (1.f + expf(-s_logit[e]));
        scores[e] = sc;
        swb[e] = sc + e_bias[e];
    }
    float gs[NGROUP];
    for (int g = 0; g < NGROUP; g++) {
        float m1 = -1e30f, m2 = -1e30f;
        for (int j = 0; j < GSIZE; j++) {
            float v = swb[g * GSIZE + j];
            if (v > m1) { m2 = m1; m1 = v; }
            else if (v > m2) m2 = v;
        }
        gs[g] = m1 + m2;
    }
    bool gsel[NGROUP] = {false};
    for (int it = 0; it < TOPKG; it++) {
        int bi = 0; float bv = -1e30f;
        for (int g = 0; g < NGROUP; g++)
            if (!gsel[g] && gs[g] > bv) { bv = gs[g]; bi = g; }
        gsel[bi] = true;
    }
    float val[E_NUM];
    for (int e = 0; e < E_NUM; e++) val[e] = gsel[e / GSIZE] ? swb[e] : 0.f;
    bool taken[E_NUM] = {false};
    int sel[TOPK];
    float denom = 0.f;
    for (int it = 0; it < TOPK; it++) {
        int bi = 0; float bv = -1e30f;
        for (int e = 0; e < E_NUM; e++)
            if (!taken[e] && val[e] > bv) { bv = val[e]; bi = e; }
        taken[bi] = true; sel[it] = bi; denom += scores[bi];
    }
    float inv = RSCALE / (denom + 1e-20f);
    for (int it = 0; it < TOPK; it++) {
        int e = sel[it];
        int slot = atomicAdd(&g_cnt[e], 1);
        g_tok[e * T_TOK + slot] = t;
        g_wgt[e * T_TOK + slot] = scores[e] * inv;
    }
}

// ---------------------------------------------------------------------------
// Unified dual GEMM: act = silu(X@Wg)*(X@Wu) [* combine]
// z<32: routed expert z (N=512). z>=32: shared expert N-slice (z-32)*512.
// Block 128x64, BK=16, ping-pong smem, 8 warps (4m x 2n), warp 32x32
// ---------------------------------------------------------------------------
__global__ __launch_bounds__(256, 2)
void k_dual(const float* __restrict__ X,
            const float* __restrict__ w_gate,
            const float* __restrict__ w_up,
            const float* __restrict__ ws_gate,
            const float* __restrict__ ws_up)
{
    const int z = blockIdx.z;
    const bool routed = z < E_NUM;
    const int e = routed ? z : 0;
    const int M = routed ? g_cnt[e] : T_TOK;
    const int m0 = blockIdx.y * 128;
    if (m0 >= M) return;
    const int NS = routed ? I_DIM : IS_DIM;   // weight/act row stride
    const int n0 = routed ? blockIdx.x * 64
                          : (z - E_NUM) * 512 + blockIdx.x * 64;
    const float* __restrict__ Wg = routed ? w_gate + (size_t)e * H_DIM * I_DIM : ws_gate;
    const float* __restrict__ Wu = routed ? w_up   + (size_t)e * H_DIM * I_DIM : ws_up;
    float* __restrict__ Act = routed ? g_act + (size_t)e * T_TOK * I_DIM : g_sact;
    const int K = H_DIM;

    __shared__ uint32_t As[2][16][132];
    __shared__ uint32_t Bgs[2][16][68];
    __shared__ uint32_t Bus[2][16][68];

    const int tid = threadIdx.x;
    const int warp = tid >> 5, lane = tid & 31;
    const int wm = warp & 3, wn = warp >> 2;
    const int grp = lane >> 2, tg = lane & 3;

    // A: 128 rows x 16 k = 512 float4, 2 per thread
    const float* aptr[2];
    bool aok[2];
    int arow[2], ac0[2];
    #pragma unroll
    for (int i = 0; i < 2; i++) {
        int idx = tid + i * 256;
        int r = idx >> 2, c0 = (idx & 3) << 2;
        arow[i] = r; ac0[i] = c0;
        int gm = m0 + r;
        bool ok = gm < M;
        int srow = 0;
        if (ok) srow = routed ? g_tok[e * T_TOK + gm] : gm;
        aptr[i] = X + (size_t)srow * K + c0;
        aok[i] = ok;
    }
    // B: 16 rows x 64 cols = 256 float4, 1 per thread (each matrix)
    const int bkr = tid >> 4, bn0 = (tid & 15) << 2;
    const float* gptr = Wg + (size_t)bkr * NS + n0 + bn0;
    const float* uptr = Wu + (size_t)bkr * NS + n0 + bn0;

    float4 rA[2], rG, rU;
    #pragma unroll
    for (int i = 0; i < 2; i++)
        rA[i] = aok[i] ? *(const float4*)(aptr[i]) : make_float4(0.f, 0.f, 0.f, 0.f);
    rG = *(const float4*)(gptr);
    rU = *(const float4*)(uptr);

    // store chunk 0 -> stage 0
    #pragma unroll
    for (int i = 0; i < 2; i++) {
        As[0][ac0[i] + 0][arow[i]] = f2tf(rA[i].x);
        As[0][ac0[i] + 1][arow[i]] = f2tf(rA[i].y);
        As[0][ac0[i] + 2][arow[i]] = f2tf(rA[i].z);
        As[0][ac0[i] + 3][arow[i]] = f2tf(rA[i].w);
    }
    Bgs[0][bkr][bn0 + 0] = f2tf(rG.x);
    Bgs[0][bkr][bn0 + 1] = f2tf(rG.y);
    Bgs[0][bkr][bn0 + 2] = f2tf(rG.z);
    Bgs[0][bkr][bn0 + 3] = f2tf(rG.w);
    Bus[0][bkr][bn0 + 0] = f2tf(rU.x);
    Bus[0][bkr][bn0 + 1] = f2tf(rU.y);
    Bus[0][bkr][bn0 + 2] = f2tf(rU.z);
    Bus[0][bkr][bn0 + 3] = f2tf(rU.w);
    __syncthreads();

    float cg[2][4][4], cu[2][4][4];
    #pragma unroll
    for (int mi = 0; mi < 2; mi++)
        #pragma unroll
        for (int ni = 0; ni < 4; ni++)
            #pragma unroll
            for (int q = 0; q < 4; q++) { cg[mi][ni][q] = 0.f; cu[mi][ni][q] = 0.f; }

    for (int k0 = 0; k0 < K; k0 += 16) {
        const int s = (k0 >> 4) & 1;
        const bool more = (k0 + 16) < K;
        if (more) {
            #pragma unroll
            for (int i = 0; i < 2; i++)
                rA[i] = aok[i] ? *(const float4*)(aptr[i] + k0 + 16)
                               : make_float4(0.f, 0.f, 0.f, 0.f);
            rG = *(const float4*)(gptr + (size_t)(k0 + 16) * NS);
            rU = *(const float4*)(uptr + (size_t)(k0 + 16) * NS);
        }
        #pragma unroll
        for (int ks = 0; ks < 2; ks++) {
            const int kb = ks * 8;
            uint32_t af[2][4];
            #pragma unroll
            for (int mi = 0; mi < 2; mi++) {
                int m = wm * 32 + mi * 16 + grp;
                af[mi][0] = As[s][kb + tg][m];
                af[mi][1] = As[s][kb + tg][m + 8];
                af[mi][2] = As[s][kb + tg + 4][m];
                af[mi][3] = As[s][kb + tg + 4][m + 8];
            }
            #pragma unroll
            for (int ni = 0; ni < 4; ni++) {
                int n = wn * 32 + ni * 8 + grp;
                uint32_t bg0 = Bgs[s][kb + tg][n];
                uint32_t bg1 = Bgs[s][kb + tg + 4][n];
                uint32_t bu0 = Bus[s][kb + tg][n];
                uint32_t bu1 = Bus[s][kb + tg + 4][n];
                #pragma unroll
                for (int mi = 0; mi < 2; mi++) {
                    mma_tf32(cg[mi][ni], af[mi][0], af[mi][1], af[mi][2], af[mi][3], bg0, bg1);
                    mma_tf32(cu[mi][ni], af[mi][0], af[mi][1], af[mi][2], af[mi][3], bu0, bu1);
                }
            }
        }
        if (more) {
            const int d = s ^ 1;
            #pragma unroll
            for (int i = 0; i < 2; i++) {
                As[d][ac0[i] + 0][arow[i]] = f2tf(rA[i].x);
                As[d][ac0[i] + 1][arow[i]] = f2tf(rA[i].y);
                As[d][ac0[i] + 2][arow[i]] = f2tf(rA[i].z);
                As[d][ac0[i] + 3][arow[i]] = f2tf(rA[i].w);
            }
            Bgs[d][bkr][bn0 + 0] = f2tf(rG.x);
            Bgs[d][bkr][bn0 + 1] = f2tf(rG.y);
            Bgs[d][bkr][bn0 + 2] = f2tf(rG.z);
            Bgs[d][bkr][bn0 + 3] = f2tf(rG.w);
            Bus[d][bkr][bn0 + 0] = f2tf(rU.x);
            Bus[d][bkr][bn0 + 1] = f2tf(rU.y);
            Bus[d][bkr][bn0 + 2] = f2tf(rU.z);
            Bus[d][bkr][bn0 + 3] = f2tf(rU.w);
            __syncthreads();
        }
    }

    #pragma unroll
    for (int mi = 0; mi < 2; mi++) {
        int r0 = m0 + wm * 32 + mi * 16 + grp;
        int r1 = r0 + 8;
        float w0 = 1.f, w1 = 1.f;
        if (routed) {
            if (r0 < M) w0 = g_wgt[e * T_TOK + r0];
            if (r1 < M) w1 = g_wgt[e * T_TOK + r1];
        }
        #pragma unroll
        for (int ni = 0; ni < 4; ni++) {
            int col = n0 + wn * 32 + ni * 8 + tg * 2;
            if (r0 < M) {
                float2 v;
                v.x = silu_f(cg[mi][ni][0]) * cu[mi][ni][0] * w0;
                v.y = silu_f(cg[mi][ni][1]) * cu[mi][ni][1] * w0;
                *(float2*)(Act + (size_t)r0 * NS + col) = v;
            }
            if (r1 < M) {
                float2 v;
                v.x = silu_f(cg[mi][ni][2]) * cu[mi][ni][2] * w1;
                v.y = silu_f(cg[mi][ni][3]) * cu[mi][ni][3] * w1;
                *(float2*)(Act + (size_t)r1 * NS + col) = v;
            }
        }
    }
}

// ---------------------------------------------------------------------------
// Unified down-proj: out += act @ Wd  (atomicAdd into zeroed out)
// z<32: routed expert z (K=512). z>=32: shared expert K-slice (z-32)*512.
// Block 128x128, BK=16, ping-pong, 8 warps (2m x 4n), warp 64x32
// ---------------------------------------------------------------------------
__global__ __launch_bounds__(256, 2)
void k_down(const float* __restrict__ w_down,
            const float* __restrict__ ws_down,
            float* __restrict__ Out)
{
    const int z = blockIdx.z;
    const bool routed = z < E_NUM;
    const int e = routed ? z : 0;
    const int M = routed ? g_cnt[e] : T_TOK;
    const int m0 = blockIdx.y * 128;
    if (m0 >= M) return;
    const int n0 = blockIdx.x * 128;
    const int koff = routed ? 0 : (z - E_NUM) * 512;
    const float* __restrict__ A = routed ? g_act + (size_t)e * T_TOK * I_DIM : g_sact;
    const int AS = routed ? I_DIM : IS_DIM;
    const float* __restrict__ B = routed ? w_down + (size_t)e * I_DIM * H_DIM
                                         : ws_down + (size_t)koff * H_DIM;
    const int K = 512;
    const int N = H_DIM;

    __shared__ uint32_t As[2][16][132];
    __shared__ uint32_t Bs[2][16][132];

    const int tid = threadIdx.x;
    const int warp = tid >> 5, lane = tid & 31;
    const int wm = warp & 1, wn = warp >> 1;
    const int grp = lane >> 2, tg = lane & 3;

    // A: 128 x 16 = 512 float4, 2/thread
    const float* aptr[2];
    bool aok[2];
    int arow[2], ac0[2];
    #pragma unroll
    for (int i = 0; i < 2; i++) {
        int idx = tid + i * 256;
        int r = idx >> 2, c0 = (idx & 3) << 2;
        arow[i] = r; ac0[i] = c0;
        bool ok = (m0 + r) < M;
        aptr[i] = A + (size_t)(ok ? (m0 + r) : 0) * AS + koff + c0;
        aok[i] = ok;
    }
    // B: 16 x 128 = 512 float4, 2/thread
    const float* bptr[2];
    int bkr[2], bn0[2];
    #pragma unroll
    for (int i = 0; i < 2; i++) {
        int idx = tid + i * 256;
        bkr[i] = idx >> 5; bn0[i] = (idx & 31) << 2;
        bptr[i] = B + (size_t)bkr[i] * N + n0 + bn0[i];
    }

    float4 rA[2], rB[2];
    #pragma unroll
    for (int i = 0; i < 2; i++) {
        rA[i] = aok[i] ? *(const float4*)(aptr[i]) : make_float4(0.f, 0.f, 0.f, 0.f);
        rB[i] = *(const float4*)(bptr[i]);
    }
    #pragma unroll
    for (int i = 0; i < 2; i++) {
        As[0][ac0[i] + 0][arow[i]] = f2tf(rA[i].x);
        As[0][ac0[i] + 1][arow[i]] = f2tf(rA[i].y);
        As[0][ac0[i] + 2][arow[i]] = f2tf(rA[i].z);
        As[0][ac0[i] + 3][arow[i]] = f2tf(rA[i].w);
        Bs[0][bkr[i]][bn0[i] + 0] = f2tf(rB[i].x);
        Bs[0][bkr[i]][bn0[i] + 1] = f2tf(rB[i].y);
        Bs[0][bkr[i]][bn0[i] + 2] = f2tf(rB[i].z);
        Bs[0][bkr[i]][bn0[i] + 3] = f2tf(rB[i].w);
    }
    __syncthreads();

    float acc[4][4][4];
    #pragma unroll
    for (int mi = 0; mi < 4; mi++)
        #pragma unroll
        for (int ni = 0; ni < 4; ni++)
            #pragma unroll
            for (int q = 0; q < 4; q++) acc[mi][ni][q] = 0.f;

    for (int k0 = 0; k0 < K; k0 += 16) {
        const int s = (k0 >> 4) & 1;
        const bool more = (k0 + 16) < K;
        if (more) {
            #pragma unroll
            for (int i = 0; i < 2; i++) {
                rA[i] = aok[i] ? *(const float4*)(aptr[i] + k0 + 16)
                               : make_float4(0.f, 0.f, 0.f, 0.f);
                rB[i] = *(const float4*)(bptr[i] + (size_t)(k0 + 16) * N);
            }
        }
        #pragma unroll
        for (int ks = 0; ks < 2; ks++) {
            const int kb = ks * 8;
            uint32_t af[4][4];
            #pragma unroll
            for (int mi = 0; mi < 4; mi++) {
                int m = wm * 64 + mi * 16 + grp;
                af[mi][0] = As[s][kb + tg][m];
                af[mi][1] = As[s][kb + tg][m + 8];
                af[mi][2] = As[s][kb + tg + 4][m];
                af[mi][3] = As[s][kb + tg + 4][m + 8];
            }
            #pragma unroll
            for (int ni = 0; ni < 4; ni++) {
                int n = wn * 32 + ni * 8 + grp;
                uint32_t b0 = Bs[s][kb + tg][n];
                uint32_t b1 = Bs[s][kb + tg + 4][n];
                #pragma unroll
                for (int mi = 0; mi < 4; mi++)
                    mma_tf32(acc[mi][ni], af[mi][0], af[mi][1], af[mi][2], af[mi][3], b0, b1);
            }
        }
        if (more) {
            const int d = s ^ 1;
            #pragma unroll
            for (int i = 0; i < 2; i++) {
                As[d][ac0[i] + 0][arow[i]] = f2tf(rA[i].x);
                As[d][ac0[i] + 1][arow[i]] = f2tf(rA[i].y);
                As[d][ac0[i] + 2][arow[i]] = f2tf(rA[i].z);
                As[d][ac0[i] + 3][arow[i]] = f2tf(rA[i].w);
                Bs[d][bkr[i]][bn0[i] + 0] = f2tf(rB[i].x);
                Bs[d][bkr[i]][bn0[i] + 1] = f2tf(rB[i].y);
                Bs[d][bkr[i]][bn0[i] + 2] = f2tf(rB[i].z);
                Bs[d][bkr[i]][bn0[i] + 3] = f2tf(rB[i].w);
            }
            __syncthreads();
        }
    }

    #pragma unroll
    for (int mi = 0; mi < 4; mi++) {
        int r0 = m0 + wm * 64 + mi * 16 + grp;
        int r1 = r0 + 8;
        int tok0 = 0, tok1 = 0;
        bool ok0 = r0 < M, ok1 = r1 < M;
        if (routed) {
            if (ok0) tok0 = g_tok[e * T_TOK + r0];
            if (ok1) tok1 = g_tok[e * T_TOK + r1];
        } else { tok0 = r0; tok1 = r1; }
        #pragma unroll
        for (int ni = 0; ni < 4; ni++) {
            int col = n0 + wn * 32 + ni * 8 + tg * 2;
            if (ok0) {
                atomicAdd(Out + (size_t)tok0 * N + col,     acc[mi][ni][0]);
                atomicAdd(Out + (size_t)tok0 * N + col + 1, acc[mi][ni][1]);
            }
            if (ok1) {
                atomicAdd(Out + (size_t)tok1 * N + col,     acc[mi][ni][2]);
                atomicAdd(Out + (size_t)tok1 * N + col + 1, acc[mi][ni][3]);
            }
        }
    }
}

// ---------------------------------------------------------------------------
extern "C" void kernel_launch(void* const* d_in, const int* in_sizes, int n_in,
                              void* d_out, int out_size)
{
    const float* x       = (const float*)d_in[0];
    const float* gate_w  = (const float*)d_in[1];
    const float* e_bias  = (const float*)d_in[2];
    const float* w_gate  = (const float*)d_in[3];
    const float* w_up    = (const float*)d_in[4];
    const float* w_down  = (const float*)d_in[5];
    const float* ws_gate = (const float*)d_in[6];
    const float* ws_up   = (const float*)d_in[7];
    const float* ws_down = (const float*)d_in[8];
    float* out = (float*)d_out;

    k_init<<<(T_TOK * H_DIM) / (256 * 4), 256>>>(out);
    k_gate_route<<<T_TOK, 256>>>(x, gate_w, e_bias);
    // all dual GEMMs (routed z=0..31, shared z=32..35)
    k_dual<<<dim3(8, 8, E_NUM + 4), 256>>>(x, w_gate, w_up, ws_gate, ws_up);
    // all down GEMMs (routed z=0..31, shared split-K z=32..35), atomic accumulate
    k_down<<<dim3(8, 8, E_NUM + 4), 256>>>(w_down, ws_down, out);
}

// round 5
// speedup vs baseline: 3.2459x; 1.2137x over previous
#include <cuda_runtime.h>
#include <math.h>
#include <stdint.h>

#define T_TOK 1024
#define H_DIM 1024
#define E_NUM 32
#define I_DIM 512
#define IS_DIM 2048
#define NGROUP 8
#define GSIZE 4
#define TOPKG 4
#define TOPK 8
#define RSCALE 2.5f

// Scratch
__device__ float g_act[(size_t)E_NUM * T_TOK * I_DIM];
__device__ float g_sact[(size_t)T_TOK * IS_DIM];
__device__ int   g_cnt[E_NUM];
__device__ int   g_tok[E_NUM * T_TOK];
__device__ float g_wgt[E_NUM * T_TOK];

__device__ __forceinline__ float silu_f(float v) { return v / (1.f + expf(-v)); }

__device__ __forceinline__ uint32_t f2tf(float f) {
    uint32_t u;
    asm("cvt.rna.tf32.f32 %0, %1;" : "=r"(u) : "f"(f));
    return u;
}

__device__ __forceinline__ void mma_tf32(float* c,
                                         uint32_t a0, uint32_t a1, uint32_t a2, uint32_t a3,
                                         uint32_t b0, uint32_t b1)
{
    asm volatile(
        "mma.sync.aligned.m16n8k8.row.col.f32.tf32.tf32.f32 "
        "{%0,%1,%2,%3}, {%4,%5,%6,%7}, {%8,%9}, {%0,%1,%2,%3};\n"
        : "+f"(c[0]), "+f"(c[1]), "+f"(c[2]), "+f"(c[3])
        : "r"(a0), "r"(a1), "r"(a2), "r"(a3), "r"(b0), "r"(b1));
}

// init: zero expert counters + zero output (atomicAdd accumulation target)
__global__ void k_init(float* __restrict__ out) {
    if (blockIdx.x == 0 && threadIdx.x < E_NUM) g_cnt[threadIdx.x] = 0;
    size_t i = (size_t)blockIdx.x * 256 + threadIdx.x;
    ((float4*)out)[i] = make_float4(0.f, 0.f, 0.f, 0.f);
}

// ---------------------------------------------------------------------------
// Gate GEMV + DeepseekV3 noaux_tc routing + per-expert gather
// ---------------------------------------------------------------------------
__global__ __launch_bounds__(256) void k_gate_route(
    const float* __restrict__ x,
    const float* __restrict__ gate_w,
    const float* __restrict__ e_bias)
{
    __shared__ float s_logit[E_NUM];
    const int t = blockIdx.x;
    const int warp = threadIdx.x >> 5, lane = threadIdx.x & 31;
    const float* xr = x + (size_t)t * H_DIM;
    for (int e = warp; e < E_NUM; e += 8) {
        const float* gw = gate_w + (size_t)e * H_DIM;
        float s = 0.f;
        for (int k = lane; k < H_DIM; k += 32) s += xr[k] * gw[k];
        #pragma unroll
        for (int o = 16; o; o >>= 1) s += __shfl_xor_sync(0xffffffffu, s, o);
        if (lane == 0) s_logit[e] = s;
    }
    __syncthreads();
    if (threadIdx.x != 0) return;

    float scores[E_NUM], swb[E_NUM];
    for (int e = 0; e < E_NUM; e++) {
        float sc = 1.f / (1.f + expf(-s_logit[e]));
        scores[e] = sc;
        swb[e] = sc + e_bias[e];
    }
    float gs[NGROUP];
    for (int g = 0; g < NGROUP; g++) {
        float m1 = -1e30f, m2 = -1e30f;
        for (int j = 0; j < GSIZE; j++) {
            float v = swb[g * GSIZE + j];
            if (v > m1) { m2 = m1; m1 = v; }
            else if (v > m2) m2 = v;
        }
        gs[g] = m1 + m2;
    }
    bool gsel[NGROUP] = {false};
    for (int it = 0; it < TOPKG; it++) {
        int bi = 0; float bv = -1e30f;
        for (int g = 0; g < NGROUP; g++)
            if (!gsel[g] && gs[g] > bv) { bv = gs[g]; bi = g; }
        gsel[bi] = true;
    }
    float val[E_NUM];
    for (int e = 0; e < E_NUM; e++) val[e] = gsel[e / GSIZE] ? swb[e] : 0.f;
    bool taken[E_NUM] = {false};
    int sel[TOPK];
    float denom = 0.f;
    for (int it = 0; it < TOPK; it++) {
        int bi = 0; float bv = -1e30f;
        for (int e = 0; e < E_NUM; e++)
            if (!taken[e] && val[e] > bv) { bv = val[e]; bi = e; }
        taken[bi] = true; sel[it] = bi; denom += scores[bi];
    }
    float inv = RSCALE / (denom + 1e-20f);
    for (int it = 0; it < TOPK; it++) {
        int e = sel[it];
        int slot = atomicAdd(&g_cnt[e], 1);
        g_tok[e * T_TOK + slot] = t;
        g_wgt[e * T_TOK + slot] = scores[e] * inv;
    }
}

// ---------------------------------------------------------------------------
// Dual tf32 MMA GEMM: act = silu(X@Wg)*(X@Wu) [* combine]
// z<32: routed expert z (N=512). z>=32: shared N-slice (z-32)*512.
// Block 128x64, BK=16, ping-pong smem, 4 warps (2m x 2n), warp 64x32 (dual)
// ---------------------------------------------------------------------------
__global__ __launch_bounds__(128, 2)
void k_dual(const float* __restrict__ X,
            const float* __restrict__ w_gate,
            const float* __restrict__ w_up,
            const float* __restrict__ ws_gate,
            const float* __restrict__ ws_up)
{
    const int z = blockIdx.z;
    const bool routed = z < E_NUM;
    const int e = routed ? z : 0;
    const int M = routed ? g_cnt[e] : T_TOK;
    const int m0 = blockIdx.y * 128;
    if (m0 >= M) return;
    const int NS = routed ? I_DIM : IS_DIM;
    const int n0 = routed ? blockIdx.x * 64
                          : (z - E_NUM) * 512 + blockIdx.x * 64;
    const float* __restrict__ Wg = routed ? w_gate + (size_t)e * H_DIM * I_DIM : ws_gate;
    const float* __restrict__ Wu = routed ? w_up   + (size_t)e * H_DIM * I_DIM : ws_up;
    float* __restrict__ Act = routed ? g_act + (size_t)e * T_TOK * I_DIM : g_sact;
    const int K = H_DIM;

    __shared__ uint32_t As[2][16][136];
    __shared__ uint32_t Bgs[2][16][72];
    __shared__ uint32_t Bus[2][16][72];

    const int tid = threadIdx.x;
    const int warp = tid >> 5, lane = tid & 31;
    const int wm = warp & 1, wn = warp >> 1;
    const int grp = lane >> 2, tg = lane & 3;

    // A: 128 rows x 16 k = 512 float4, 4 per thread (128 threads)
    const float* aptr[4];
    bool aok[4];
    int arow[4], ac0[4];
    #pragma unroll
    for (int i = 0; i < 4; i++) {
        int idx = tid + i * 128;
        int r = idx >> 2, c0 = (idx & 3) << 2;
        arow[i] = r; ac0[i] = c0;
        int gm = m0 + r;
        bool ok = gm < M;
        int srow = 0;
        if (ok) srow = routed ? g_tok[e * T_TOK + gm] : gm;
        aptr[i] = X + (size_t)srow * K + c0;
        aok[i] = ok;
    }
    // B: 16 k x 64 n per matrix = 256 quad-units, 2 per thread per matrix
    const float* gptr[2];
    const float* uptr[2];
    int bkr[2], bn[2];
    #pragma unroll
    for (int i = 0; i < 2; i++) {
        int idx = tid + i * 128;
        bn[i] = idx & 63; bkr[i] = (idx >> 6) << 2;
        gptr[i] = Wg + (size_t)bkr[i] * NS + n0 + bn[i];
        uptr[i] = Wu + (size_t)bkr[i] * NS + n0 + bn[i];
    }

    float4 rA[4];
    float rG[2][4], rU[2][4];
    #pragma unroll
    for (int i = 0; i < 4; i++)
        rA[i] = aok[i] ? *(const float4*)(aptr[i]) : make_float4(0.f, 0.f, 0.f, 0.f);
    #pragma unroll
    for (int i = 0; i < 2; i++)
        #pragma unroll
        for (int j = 0; j < 4; j++) {
            rG[i][j] = gptr[i][(size_t)j * NS];
            rU[i][j] = uptr[i][(size_t)j * NS];
        }

    #pragma unroll
    for (int i = 0; i < 4; i++) {
        As[0][ac0[i] + 0][arow[i]] = f2tf(rA[i].x);
        As[0][ac0[i] + 1][arow[i]] = f2tf(rA[i].y);
        As[0][ac0[i] + 2][arow[i]] = f2tf(rA[i].z);
        As[0][ac0[i] + 3][arow[i]] = f2tf(rA[i].w);
    }
    #pragma unroll
    for (int i = 0; i < 2; i++)
        #pragma unroll
        for (int j = 0; j < 4; j++) {
            Bgs[0][bkr[i] + j][bn[i]] = f2tf(rG[i][j]);
            Bus[0][bkr[i] + j][bn[i]] = f2tf(rU[i][j]);
        }
    __syncthreads();

    float cg[4][4][4], cu[4][4][4];
    #pragma unroll
    for (int mi = 0; mi < 4; mi++)
        #pragma unroll
        for (int ni = 0; ni < 4; ni++)
            #pragma unroll
            for (int q = 0; q < 4; q++) { cg[mi][ni][q] = 0.f; cu[mi][ni][q] = 0.f; }

    for (int k0 = 0; k0 < K; k0 += 16) {
        const int s = (k0 >> 4) & 1;
        const bool more = (k0 + 16) < K;
        if (more) {
            #pragma unroll
            for (int i = 0; i < 4; i++)
                rA[i] = aok[i] ? *(const float4*)(aptr[i] + k0 + 16)
                               : make_float4(0.f, 0.f, 0.f, 0.f);
            #pragma unroll
            for (int i = 0; i < 2; i++)
                #pragma unroll
                for (int j = 0; j < 4; j++) {
                    rG[i][j] = gptr[i][(size_t)(k0 + 16 + j) * NS];
                    rU[i][j] = uptr[i][(size_t)(k0 + 16 + j) * NS];
                }
        }
        #pragma unroll
        for (int ks = 0; ks < 2; ks++) {
            const int kb = ks * 8;
            uint32_t af[4][4];
            #pragma unroll
            for (int mi = 0; mi < 4; mi++) {
                int m = wm * 64 + mi * 16 + grp;
                af[mi][0] = As[s][kb + tg][m];
                af[mi][1] = As[s][kb + tg][m + 8];
                af[mi][2] = As[s][kb + tg + 4][m];
                af[mi][3] = As[s][kb + tg + 4][m + 8];
            }
            #pragma unroll
            for (int ni = 0; ni < 4; ni++) {
                int n = wn * 32 + ni * 8 + grp;
                uint32_t bg0 = Bgs[s][kb + tg][n];
                uint32_t bg1 = Bgs[s][kb + tg + 4][n];
                uint32_t bu0 = Bus[s][kb + tg][n];
                uint32_t bu1 = Bus[s][kb + tg + 4][n];
                #pragma unroll
                for (int mi = 0; mi < 4; mi++) {
                    mma_tf32(cg[mi][ni], af[mi][0], af[mi][1], af[mi][2], af[mi][3], bg0, bg1);
                    mma_tf32(cu[mi][ni], af[mi][0], af[mi][1], af[mi][2], af[mi][3], bu0, bu1);
                }
            }
        }
        if (more) {
            const int d = s ^ 1;
            #pragma unroll
            for (int i = 0; i < 4; i++) {
                As[d][ac0[i] + 0][arow[i]] = f2tf(rA[i].x);
                As[d][ac0[i] + 1][arow[i]] = f2tf(rA[i].y);
                As[d][ac0[i] + 2][arow[i]] = f2tf(rA[i].z);
                As[d][ac0[i] + 3][arow[i]] = f2tf(rA[i].w);
            }
            #pragma unroll
            for (int i = 0; i < 2; i++)
                #pragma unroll
                for (int j = 0; j < 4; j++) {
                    Bgs[d][bkr[i] + j][bn[i]] = f2tf(rG[i][j]);
                    Bus[d][bkr[i] + j][bn[i]] = f2tf(rU[i][j]);
                }
            __syncthreads();
        }
    }

    #pragma unroll
    for (int mi = 0; mi < 4; mi++) {
        int r0 = m0 + wm * 64 + mi * 16 + grp;
        int r1 = r0 + 8;
        float w0 = 1.f, w1 = 1.f;
        if (routed) {
            if (r0 < M) w0 = g_wgt[e * T_TOK + r0];
            if (r1 < M) w1 = g_wgt[e * T_TOK + r1];
        }
        #pragma unroll
        for (int ni = 0; ni < 4; ni++) {
            int col = n0 + wn * 32 + ni * 8 + tg * 2;
            if (r0 < M) {
                float2 v;
                v.x = silu_f(cg[mi][ni][0]) * cu[mi][ni][0] * w0;
                v.y = silu_f(cg[mi][ni][1]) * cu[mi][ni][1] * w0;
                *(float2*)(Act + (size_t)r0 * NS + col) = v;
            }
            if (r1 < M) {
                float2 v;
                v.x = silu_f(cg[mi][ni][2]) * cu[mi][ni][2] * w1;
                v.y = silu_f(cg[mi][ni][3]) * cu[mi][ni][3] * w1;
                *(float2*)(Act + (size_t)r1 * NS + col) = v;
            }
        }
    }
}

// ---------------------------------------------------------------------------
// Down-proj tf32 MMA: out += act @ Wd (atomicAdd into zeroed out)
// z<32: routed expert z. z>=32: shared K-slice (z-32)*512.
// Block 128x128, BK=16, ping-pong, 4 warps (2m x 2n), warp 64x64
// ---------------------------------------------------------------------------
__global__ __launch_bounds__(128, 2)
void k_down(const float* __restrict__ w_down,
            const float* __restrict__ ws_down,
            float* __restrict__ Out)
{
    const int z = blockIdx.z;
    const bool routed = z < E_NUM;
    const int e = routed ? z : 0;
    const int M = routed ? g_cnt[e] : T_TOK;
    const int m0 = blockIdx.y * 128;
    if (m0 >= M) return;
    const int n0 = blockIdx.x * 128;
    const int koff = routed ? 0 : (z - E_NUM) * 512;
    const float* __restrict__ A = routed ? g_act + (size_t)e * T_TOK * I_DIM : g_sact;
    const int AS = routed ? I_DIM : IS_DIM;
    const float* __restrict__ B = routed ? w_down + (size_t)e * I_DIM * H_DIM
                                         : ws_down + (size_t)koff * H_DIM;
    const int K = 512;
    const int N = H_DIM;

    __shared__ uint32_t As[2][16][136];
    __shared__ uint32_t Bs[2][16][136];

    const int tid = threadIdx.x;
    const int warp = tid >> 5, lane = tid & 31;
    const int wm = warp & 1, wn = warp >> 1;
    const int grp = lane >> 2, tg = lane & 3;

    // A: 128 x 16 = 512 float4, 4/thread
    const float* aptr[4];
    bool aok[4];
    int arow[4], ac0[4];
    #pragma unroll
    for (int i = 0; i < 4; i++) {
        int idx = tid + i * 128;
        int r = idx >> 2, c0 = (idx & 3) << 2;
        arow[i] = r; ac0[i] = c0;
        bool ok = (m0 + r) < M;
        aptr[i] = A + (size_t)(ok ? (m0 + r) : 0) * AS + koff + c0;
        aok[i] = ok;
    }
    // B: 16 k x 128 n = 512 quad-units, 4/thread
    const float* bptr[4];
    int bkr[4], bn[4];
    #pragma unroll
    for (int i = 0; i < 4; i++) {
        int idx = tid + i * 128;
        bn[i] = idx & 127; bkr[i] = (idx >> 7) << 2;
        bptr[i] = B + (size_t)bkr[i] * N + n0 + bn[i];
    }

    float4 rA[4];
    float rB[4][4];
    #pragma unroll
    for (int i = 0; i < 4; i++) {
        rA[i] = aok[i] ? *(const float4*)(aptr[i]) : make_float4(0.f, 0.f, 0.f, 0.f);
        #pragma unroll
        for (int j = 0; j < 4; j++) rB[i][j] = bptr[i][(size_t)j * N];
    }
    #pragma unroll
    for (int i = 0; i < 4; i++) {
        As[0][ac0[i] + 0][arow[i]] = f2tf(rA[i].x);
        As[0][ac0[i] + 1][arow[i]] = f2tf(rA[i].y);
        As[0][ac0[i] + 2][arow[i]] = f2tf(rA[i].z);
        As[0][ac0[i] + 3][arow[i]] = f2tf(rA[i].w);
        #pragma unroll
        for (int j = 0; j < 4; j++)
            Bs[0][bkr[i] + j][bn[i]] = f2tf(rB[i][j]);
    }
    __syncthreads();

    float acc[4][8][4];
    #pragma unroll
    for (int mi = 0; mi < 4; mi++)
        #pragma unroll
        for (int ni = 0; ni < 8; ni++)
            #pragma unroll
            for (int q = 0; q < 4; q++) acc[mi][ni][q] = 0.f;

    for (int k0 = 0; k0 < K; k0 += 16) {
        const int s = (k0 >> 4) & 1;
        const bool more = (k0 + 16) < K;
        if (more) {
            #pragma unroll
            for (int i = 0; i < 4; i++) {
                rA[i] = aok[i] ? *(const float4*)(aptr[i] + k0 + 16)
                               : make_float4(0.f, 0.f, 0.f, 0.f);
                #pragma unroll
                for (int j = 0; j < 4; j++)
                    rB[i][j] = bptr[i][(size_t)(k0 + 16 + j) * N];
            }
        }
        #pragma unroll
        for (int ks = 0; ks < 2; ks++) {
            const int kb = ks * 8;
            uint32_t af[4][4];
            #pragma unroll
            for (int mi = 0; mi < 4; mi++) {
                int m = wm * 64 + mi * 16 + grp;
                af[mi][0] = As[s][kb + tg][m];
                af[mi][1] = As[s][kb + tg][m + 8];
                af[mi][2] = As[s][kb + tg + 4][m];
                af[mi][3] = As[s][kb + tg + 4][m + 8];
            }
            #pragma unroll
            for (int ni = 0; ni < 8; ni++) {
                int n = wn * 64 + ni * 8 + grp;
                uint32_t b0 = Bs[s][kb + tg][n];
                uint32_t b1 = Bs[s][kb + tg + 4][n];
                #pragma unroll
                for (int mi = 0; mi < 4; mi++)
                    mma_tf32(acc[mi][ni], af[mi][0], af[mi][1], af[mi][2], af[mi][3], b0, b1);
            }
        }
        if (more) {
            const int d = s ^ 1;
            #pragma unroll
            for (int i = 0; i < 4; i++) {
                As[d][ac0[i] + 0][arow[i]] = f2tf(rA[i].x);
                As[d][ac0[i] + 1][arow[i]] = f2tf(rA[i].y);
                As[d][ac0[i] + 2][arow[i]] = f2tf(rA[i].z);
                As[d][ac0[i] + 3][arow[i]] = f2tf(rA[i].w);
                #pragma unroll
                for (int j = 0; j < 4; j++)
                    Bs[d][bkr[i] + j][bn[i]] = f2tf(rB[i][j]);
            }
            __syncthreads();
        }
    }

    #pragma unroll
    for (int mi = 0; mi < 4; mi++) {
        int r0 = m0 + wm * 64 + mi * 16 + grp;
        int r1 = r0 + 8;
        int tok0 = 0, tok1 = 0;
        bool ok0 = r0 < M, ok1 = r1 < M;
        if (routed) {
            if (ok0) tok0 = g_tok[e * T_TOK + r0];
            if (ok1) tok1 = g_tok[e * T_TOK + r1];
        } else { tok0 = r0; tok1 = r1; }
        #pragma unroll
        for (int ni = 0; ni < 8; ni++) {
            int col = n0 + wn * 64 + ni * 8 + tg * 2;
            if (ok0) {
                atomicAdd(Out + (size_t)tok0 * N + col,     acc[mi][ni][0]);
                atomicAdd(Out + (size_t)tok0 * N + col + 1, acc[mi][ni][1]);
            }
            if (ok1) {
                atomicAdd(Out + (size_t)tok1 * N + col,     acc[mi][ni][2]);
                atomicAdd(Out + (size_t)tok1 * N + col + 1, acc[mi][ni][3]);
            }
        }
    }
}

// ---------------------------------------------------------------------------
extern "C" void kernel_launch(void* const* d_in, const int* in_sizes, int n_in,
                              void* d_out, int out_size)
{
    const float* x       = (const float*)d_in[0];
    const float* gate_w  = (const float*)d_in[1];
    const float* e_bias  = (const float*)d_in[2];
    const float* w_gate  = (const float*)d_in[3];
    const float* w_up    = (const float*)d_in[4];
    const float* w_down  = (const float*)d_in[5];
    const float* ws_gate = (const float*)d_in[6];
    const float* ws_up   = (const float*)d_in[7];
    const float* ws_down = (const float*)d_in[8];
    float* out = (float*)d_out;

    k_init<<<(T_TOK * H_DIM) / (256 * 4), 256>>>(out);
    k_gate_route<<<T_TOK, 256>>>(x, gate_w, e_bias);
    // dual GEMMs: routed z=0..31, shared z=32..35
    k_dual<<<dim3(8, 8, E_NUM + 4), 128>>>(x, w_gate, w_up, ws_gate, ws_up);
    // down GEMMs: routed z=0..31, shared split-K z=32..35; atomic accumulate
    k_down<<<dim3(8, 8, E_NUM + 4), 128>>>(w_down, ws_down, out);
}

// round 6
// speedup vs baseline: 3.5251x; 1.0860x over previous
#include <cuda_runtime.h>
#include <math.h>
#include <stdint.h>

#define T_TOK 1024
#define H_DIM 1024
#define E_NUM 32
#define I_DIM 512
#define IS_DIM 2048
#define NGROUP 8
#define GSIZE 4
#define TOPKG 4
#define TOPK 8
#define RSCALE 2.5f

// Scratch: activations stored as tf32 bit patterns (pre-converted)
__device__ uint32_t g_xtf[(size_t)T_TOK * H_DIM];
__device__ uint32_t g_act[(size_t)E_NUM * T_TOK * I_DIM];
__device__ uint32_t g_sact[(size_t)T_TOK * IS_DIM];
__device__ int   g_cnt[E_NUM];
__device__ int   g_tok[E_NUM * T_TOK];
__device__ float g_wgt[E_NUM * T_TOK];

__device__ __forceinline__ float silu_f(float v) { return v / (1.f + expf(-v)); }

__device__ __forceinline__ uint32_t f2tf(float f) {
    uint32_t u;
    asm("cvt.rna.tf32.f32 %0, %1;" : "=r"(u) : "f"(f));
    return u;
}

__device__ __forceinline__ uint32_t smem_u32(const void* p) {
    uint32_t a;
    asm("{ .reg .u64 t; cvta.to.shared.u64 t, %1; cvt.u32.u64 %0, t; }" : "=r"(a) : "l"(p));
    return a;
}

__device__ __forceinline__ void mma_tf32(float* c,
                                         uint32_t a0, uint32_t a1, uint32_t a2, uint32_t a3,
                                         uint32_t b0, uint32_t b1)
{
    asm volatile(
        "mma.sync.aligned.m16n8k8.row.col.f32.tf32.tf32.f32 "
        "{%0,%1,%2,%3}, {%4,%5,%6,%7}, {%8,%9}, {%0,%1,%2,%3};\n"
        : "+f"(c[0]), "+f"(c[1]), "+f"(c[2]), "+f"(c[3])
        : "r"(a0), "r"(a1), "r"(a2), "r"(a3), "r"(b0), "r"(b1));
}

#define CP16(dst, src, sz) \
    asm volatile("cp.async.cg.shared.global [%0], [%1], 16, %2;" \
                 :: "r"(dst), "l"(src), "r"(sz) : "memory")
#define CP_COMMIT() asm volatile("cp.async.commit_group;" ::: "memory")
#define CP_WAIT1()  asm volatile("cp.async.wait_group 1;" ::: "memory")

// init: zero expert counters + zero output (atomicAdd target)
__global__ void k_init(float* __restrict__ out) {
    if (blockIdx.x == 0 && threadIdx.x < E_NUM) g_cnt[threadIdx.x] = 0;
    size_t i = (size_t)blockIdx.x * 256 + threadIdx.x;
    ((float4*)out)[i] = make_float4(0.f, 0.f, 0.f, 0.f);
}

// convert X -> tf32 bits once
__global__ void k_xtf(const float* __restrict__ x) {
    size_t i = (size_t)blockIdx.x * 256 + threadIdx.x;
    float4 v = ((const float4*)x)[i];
    ((uint4*)g_xtf)[i] = make_uint4(f2tf(v.x), f2tf(v.y), f2tf(v.z), f2tf(v.w));
}

// ---------------------------------------------------------------------------
// Gate GEMV + DeepseekV3 noaux_tc routing + per-expert gather
// ---------------------------------------------------------------------------
__global__ __launch_bounds__(256) void k_gate_route(
    const float* __restrict__ x,
    const float* __restrict__ gate_w,
    const float* __restrict__ e_bias)
{
    __shared__ float s_logit[E_NUM];
    const int t = blockIdx.x;
    const int warp = threadIdx.x >> 5, lane = threadIdx.x & 31;
    const float* xr = x + (size_t)t * H_DIM;
    for (int e = warp; e < E_NUM; e += 8) {
        const float* gw = gate_w + (size_t)e * H_DIM;
        float s = 0.f;
        for (int k = lane; k < H_DIM; k += 32) s += xr[k] * gw[k];
        #pragma unroll
        for (int o = 16; o; o >>= 1) s += __shfl_xor_sync(0xffffffffu, s, o);
        if (lane == 0) s_logit[e] = s;
    }
    __syncthreads();
    if (threadIdx.x != 0) return;

    float scores[E_NUM], swb[E_NUM];
    for (int e = 0; e < E_NUM; e++) {
        float sc = 1.f / (1.f + expf(-s_logit[e]));
        scores[e] = sc;
        swb[e] = sc + e_bias[e];
    }
    float gs[NGROUP];
    for (int g = 0; g < NGROUP; g++) {
        float m1 = -1e30f, m2 = -1e30f;
        for (int j = 0; j < GSIZE; j++) {
            float v = swb[g * GSIZE + j];
            if (v > m1) { m2 = m1; m1 = v; }
            else if (v > m2) m2 = v;
        }
        gs[g] = m1 + m2;
    }
    bool gsel[NGROUP] = {false};
    for (int it = 0; it < TOPKG; it++) {
        int bi = 0; float bv = -1e30f;
        for (int g = 0; g < NGROUP; g++)
            if (!gsel[g] && gs[g] > bv) { bv = gs[g]; bi = g; }
        gsel[bi] = true;
    }
    float val[E_NUM];
    for (int e = 0; e < E_NUM; e++) val[e] = gsel[e / GSIZE] ? swb[e] : 0.f;
    bool taken[E_NUM] = {false};
    int sel[TOPK];
    float denom = 0.f;
    for (int it = 0; it < TOPK; it++) {
        int bi = 0; float bv = -1e30f;
        for (int e = 0; e < E_NUM; e++)
            if (!taken[e] && val[e] > bv) { bv = val[e]; bi = e; }
        taken[bi] = true; sel[it] = bi; denom += scores[bi];
    }
    float inv = RSCALE / (denom + 1e-20f);
    for (int it = 0; it < TOPK; it++) {
        int e = sel[it];
        int slot = atomicAdd(&g_cnt[e], 1);
        g_tok[e * T_TOK + slot] = t;
        g_wgt[e * T_TOK + slot] = scores[e] * inv;
    }
}

// ---------------------------------------------------------------------------
// Shared layout constants (per stage, in 32-bit words):
//   A: 128 rows x 20 words (16 k + 4 pad) = 2560 words (conflict-free: 20m+k)
//   B: 16 rows x (row words), 16B-chunk XOR swizzle: phys_chunk = c ^ (tg<<1)
// Stage total = 4608 words = 18432 B; 3 stages = 55296 B (dynamic smem).
// ---------------------------------------------------------------------------
#define STAGE_W 4608
#define STAGE_B 18432
#define SMEM_BYTES (3 * STAGE_B)

// ---------------------------------------------------------------------------
// Dual tf32 MMA GEMM (cp.async, 3-stage): act = silu(X@Wg)*(X@Wu) [* combine]
// Block 128x64, BK=16, 4 warps (2m x 2n), warp 64x32 dual.
// z<32: routed expert z. z>=32: shared N-slice (z-32)*512.
// ---------------------------------------------------------------------------
__global__ __launch_bounds__(128, 3)
void k_dual(const float* __restrict__ w_gate,
            const float* __restrict__ w_up,
            const float* __restrict__ ws_gate,
            const float* __restrict__ ws_up)
{
    extern __shared__ uint32_t sm[];
    const int z = blockIdx.z;
    const bool routed = z < E_NUM;
    const int e = routed ? z : 0;
    const int M = routed ? g_cnt[e] : T_TOK;
    const int m0 = blockIdx.y * 128;
    if (m0 >= M) return;
    const int NS = routed ? I_DIM : IS_DIM;
    const int n0 = routed ? blockIdx.x * 64
                          : (z - E_NUM) * 512 + blockIdx.x * 64;
    const float* __restrict__ Wg = routed ? w_gate + (size_t)e * H_DIM * I_DIM : ws_gate;
    const float* __restrict__ Wu = routed ? w_up   + (size_t)e * H_DIM * I_DIM : ws_up;
    uint32_t* __restrict__ Act = routed ? g_act + (size_t)e * T_TOK * I_DIM : g_sact;

    const uint32_t sb = smem_u32(sm);
    const int tid = threadIdx.x;
    const int warp = tid >> 5, lane = tid & 31;
    const int wm = warp & 1, wn = warp >> 1;
    const int grp = lane >> 2, tg = lane & 3;

    // cp.async A: 128 rows x 16k, 4 units/thread (16B each)
    const uint32_t* aSrc[4];
    uint32_t aDst[4], aSz[4];
    #pragma unroll
    for (int u = 0; u < 4; u++) {
        int idx = tid + u * 128;
        int am = idx >> 2, ak4 = idx & 3;
        int gm = m0 + am;
        bool ok = gm < M;
        int srow = ok ? (routed ? g_tok[e * T_TOK + gm] : gm) : 0;
        aSrc[u] = g_xtf + (size_t)srow * H_DIM + ak4 * 4;
        aDst[u] = (uint32_t)(am * 80 + ak4 * 16);
        aSz[u] = ok ? 16u : 0u;
    }
    // cp.async B: 16 rows x 64n per matrix, 2 units/thread/matrix
    const float* gSrc[2];
    const float* uSrc[2];
    uint32_t bDst[2];
    #pragma unroll
    for (int u = 0; u < 2; u++) {
        int idx = tid + u * 128;
        int bk = idx >> 4, bc = idx & 15;
        int cph = bc ^ ((bk & 3) << 1);
        gSrc[u] = Wg + (size_t)bk * NS + n0 + bc * 4;
        uSrc[u] = Wu + (size_t)bk * NS + n0 + bc * 4;
        bDst[u] = (uint32_t)(10240 + bk * 256 + cph * 16);
    }

    // fragment word offsets
    int aw[4];
    #pragma unroll
    for (int mi = 0; mi < 4; mi++)
        aw[mi] = (wm * 64 + mi * 16 + grp) * 20 + tg;
    int bw[4];
    #pragma unroll
    for (int ni = 0; ni < 4; ni++) {
        int n = wn * 32 + ni * 8 + grp;
        int cph = (n >> 2) ^ (tg << 1);
        bw[ni] = 2560 + tg * 64 + cph * 4 + (n & 3);
    }

    const int NC = H_DIM / 16;  // 64
    // prologue: stages 0, 1
    #pragma unroll
    for (int c = 0; c < 2; c++) {
        uint32_t st = sb + c * STAGE_B;
        #pragma unroll
        for (int u = 0; u < 4; u++) CP16(st + aDst[u], aSrc[u] + c * 16, aSz[u]);
        #pragma unroll
        for (int u = 0; u < 2; u++) {
            CP16(st + bDst[u],        gSrc[u] + (size_t)c * 16 * NS, 16u);
            CP16(st + bDst[u] + 4096, uSrc[u] + (size_t)c * 16 * NS, 16u);
        }
        CP_COMMIT();
    }

    float cg[4][4][4], cu[4][4][4];
    #pragma unroll
    for (int mi = 0; mi < 4; mi++)
        #pragma unroll
        for (int ni = 0; ni < 4; ni++)
            #pragma unroll
            for (int q = 0; q < 4; q++) { cg[mi][ni][q] = 0.f; cu[mi][ni][q] = 0.f; }

    for (int c = 0; c < NC; c++) {
        CP_WAIT1();
        __syncthreads();
        // issue stage c+2
        if (c + 2 < NC) {
            int c2 = c + 2;
            uint32_t st = sb + (c2 % 3) * STAGE_B;
            #pragma unroll
            for (int u = 0; u < 4; u++) CP16(st + aDst[u], aSrc[u] + c2 * 16, aSz[u]);
            #pragma unroll
            for (int u = 0; u < 2; u++) {
                CP16(st + bDst[u],        gSrc[u] + (size_t)c2 * 16 * NS, 16u);
                CP16(st + bDst[u] + 4096, uSrc[u] + (size_t)c2 * 16 * NS, 16u);
            }
        }
        CP_COMMIT();
        const uint32_t* S = sm + (c % 3) * STAGE_W;
        #pragma unroll
        for (int ks = 0; ks < 2; ks++) {
            const int kb = ks * 8;
            uint32_t af[4][4];
            #pragma unroll
            for (int mi = 0; mi < 4; mi++) {
                af[mi][0] = S[aw[mi] + kb];
                af[mi][1] = S[aw[mi] + 160 + kb];
                af[mi][2] = S[aw[mi] + kb + 4];
                af[mi][3] = S[aw[mi] + 160 + kb + 4];
            }
            #pragma unroll
            for (int ni = 0; ni < 4; ni++) {
                uint32_t bg0 = f2tf(__uint_as_float(S[bw[ni] + kb * 64]));
                uint32_t bg1 = f2tf(__uint_as_float(S[bw[ni] + (kb + 4) * 64]));
                uint32_t bu0 = f2tf(__uint_as_float(S[bw[ni] + 1024 + kb * 64]));
                uint32_t bu1 = f2tf(__uint_as_float(S[bw[ni] + 1024 + (kb + 4) * 64]));
                #pragma unroll
                for (int mi = 0; mi < 4; mi++) {
                    mma_tf32(cg[mi][ni], af[mi][0], af[mi][1], af[mi][2], af[mi][3], bg0, bg1);
                    mma_tf32(cu[mi][ni], af[mi][0], af[mi][1], af[mi][2], af[mi][3], bu0, bu1);
                }
            }
        }
    }

    // epilogue: silu(g)*u (* wgt), store tf32 bits
    #pragma unroll
    for (int mi = 0; mi < 4; mi++) {
        int r0 = m0 + wm * 64 + mi * 16 + grp;
        int r1 = r0 + 8;
        float w0 = 1.f, w1 = 1.f;
        if (routed) {
            if (r0 < M) w0 = g_wgt[e * T_TOK + r0];
            if (r1 < M) w1 = g_wgt[e * T_TOK + r1];
        }
        #pragma unroll
        for (int ni = 0; ni < 4; ni++) {
            int col = n0 + wn * 32 + ni * 8 + tg * 2;
            if (r0 < M) {
                uint2 v;
                v.x = f2tf(silu_f(cg[mi][ni][0]) * cu[mi][ni][0] * w0);
                v.y = f2tf(silu_f(cg[mi][ni][1]) * cu[mi][ni][1] * w0);
                *(uint2*)(Act + (size_t)r0 * NS + col) = v;
            }
            if (r1 < M) {
                uint2 v;
                v.x = f2tf(silu_f(cg[mi][ni][2]) * cu[mi][ni][2] * w1);
                v.y = f2tf(silu_f(cg[mi][ni][3]) * cu[mi][ni][3] * w1);
                *(uint2*)(Act + (size_t)r1 * NS + col) = v;
            }
        }
    }
}

// ---------------------------------------------------------------------------
// Down-proj tf32 MMA (cp.async, 3-stage): out += act @ Wd (atomicAdd)
// Block 128x128, BK=16, 4 warps (2m x 2n), warp 64x64.
// z<32: routed expert z. z>=32: shared K-slice (z-32)*512.
// ---------------------------------------------------------------------------
__global__ __launch_bounds__(128, 3)
void k_down(const float* __restrict__ w_down,
            const float* __restrict__ ws_down,
            float* __restrict__ Out)
{
    extern __shared__ uint32_t sm[];
    const int z = blockIdx.z;
    const bool routed = z < E_NUM;
    const int e = routed ? z : 0;
    const int M = routed ? g_cnt[e] : T_TOK;
    const int m0 = blockIdx.y * 128;
    if (m0 >= M) return;
    const int n0 = blockIdx.x * 128;
    const int koff = routed ? 0 : (z - E_NUM) * 512;
    const uint32_t* __restrict__ A = routed ? g_act + (size_t)e * T_TOK * I_DIM : g_sact;
    const int AS = routed ? I_DIM : IS_DIM;
    const float* __restrict__ B = routed ? w_down + (size_t)e * I_DIM * H_DIM
                                         : ws_down + (size_t)koff * H_DIM;
    const int N = H_DIM;

    const uint32_t sb = smem_u32(sm);
    const int tid = threadIdx.x;
    const int warp = tid >> 5, lane = tid & 31;
    const int wm = warp & 1, wn = warp >> 1;
    const int grp = lane >> 2, tg = lane & 3;

    // cp.async A: 128 rows x 16k, 4 units/thread
    const uint32_t* aSrc[4];
    uint32_t aDst[4], aSz[4];
    #pragma unroll
    for (int u = 0; u < 4; u++) {
        int idx = tid + u * 128;
        int am = idx >> 2, ak4 = idx & 3;
        int gm = m0 + am;
        bool ok = gm < M;
        aSrc[u] = A + (size_t)(ok ? gm : 0) * AS + koff + ak4 * 4;
        aDst[u] = (uint32_t)(am * 80 + ak4 * 16);
        aSz[u] = ok ? 16u : 0u;
    }
    // cp.async B: 16 rows x 128n, 4 units/thread
    const float* bSrc[4];
    uint32_t bDst[4];
    #pragma unroll
    for (int u = 0; u < 4; u++) {
        int idx = tid + u * 128;
        int bk = idx >> 5, bc = idx & 31;
        int cph = bc ^ ((bk & 3) << 1);
        bSrc[u] = B + (size_t)bk * N + n0 + bc * 4;
        bDst[u] = (uint32_t)(10240 + bk * 512 + cph * 16);
    }

    int aw[4];
    #pragma unroll
    for (int mi = 0; mi < 4; mi++)
        aw[mi] = (wm * 64 + mi * 16 + grp) * 20 + tg;
    int bw[8];
    #pragma unroll
    for (int ni = 0; ni < 8; ni++) {
        int n = wn * 64 + ni * 8 + grp;
        int cph = (n >> 2) ^ (tg << 1);
        bw[ni] = 2560 + tg * 128 + cph * 4 + (n & 3);
    }

    const int NC = 512 / 16;  // 32
    #pragma unroll
    for (int c = 0; c < 2; c++) {
        uint32_t st = sb + c * STAGE_B;
        #pragma unroll
        for (int u = 0; u < 4; u++) {
            CP16(st + aDst[u], aSrc[u] + c * 16, aSz[u]);
            CP16(st + bDst[u], bSrc[u] + (size_t)c * 16 * N, 16u);
        }
        CP_COMMIT();
    }

    float acc[4][8][4];
    #pragma unroll
    for (int mi = 0; mi < 4; mi++)
        #pragma unroll
        for (int ni = 0; ni < 8; ni++)
            #pragma unroll
            for (int q = 0; q < 4; q++) acc[mi][ni][q] = 0.f;

    for (int c = 0; c < NC; c++) {
        CP_WAIT1();
        __syncthreads();
        if (c + 2 < NC) {
            int c2 = c + 2;
            uint32_t st = sb + (c2 % 3) * STAGE_B;
            #pragma unroll
            for (int u = 0; u < 4; u++) {
                CP16(st + aDst[u], aSrc[u] + c2 * 16, aSz[u]);
                CP16(st + bDst[u], bSrc[u] + (size_t)c2 * 16 * N, 16u);
            }
        }
        CP_COMMIT();
        const uint32_t* S = sm + (c % 3) * STAGE_W;
        #pragma unroll
        for (int ks = 0; ks < 2; ks++) {
            const int kb = ks * 8;
            uint32_t af[4][4];
            #pragma unroll
            for (int mi = 0; mi < 4; mi++) {
                af[mi][0] = S[aw[mi] + kb];
                af[mi][1] = S[aw[mi] + 160 + kb];
                af[mi][2] = S[aw[mi] + kb + 4];
                af[mi][3] = S[aw[mi] + 160 + kb + 4];
            }
            #pragma unroll
            for (int ni = 0; ni < 8; ni++) {
                uint32_t b0 = f2tf(__uint_as_float(S[bw[ni] + kb * 128]));
                uint32_t b1 = f2tf(__uint_as_float(S[bw[ni] + (kb + 4) * 128]));
                #pragma unroll
                for (int mi = 0; mi < 4; mi++)
                    mma_tf32(acc[mi][ni], af[mi][0], af[mi][1], af[mi][2], af[mi][3], b0, b1);
            }
        }
    }

    #pragma unroll
    for (int mi = 0; mi < 4; mi++) {
        int r0 = m0 + wm * 64 + mi * 16 + grp;
        int r1 = r0 + 8;
        int tok0 = 0, tok1 = 0;
        bool ok0 = r0 < M, ok1 = r1 < M;
        if (routed) {
            if (ok0) tok0 = g_tok[e * T_TOK + r0];
            if (ok1) tok1 = g_tok[e * T_TOK + r1];
        } else { tok0 = r0; tok1 = r1; }
        #pragma unroll
        for (int ni = 0; ni < 8; ni++) {
            int col = n0 + wn * 64 + ni * 8 + tg * 2;
            if (ok0) {
                atomicAdd(Out + (size_t)tok0 * N + col,     acc[mi][ni][0]);
                atomicAdd(Out + (size_t)tok0 * N + col + 1, acc[mi][ni][1]);
            }
            if (ok1) {
                atomicAdd(Out + (size_t)tok1 * N + col,     acc[mi][ni][2]);
                atomicAdd(Out + (size_t)tok1 * N + col + 1, acc[mi][ni][3]);
            }
        }
    }
}

// ---------------------------------------------------------------------------
extern "C" void kernel_launch(void* const* d_in, const int* in_sizes, int n_in,
                              void* d_out, int out_size)
{
    const float* x       = (const float*)d_in[0];
    const float* gate_w  = (const float*)d_in[1];
    const float* e_bias  = (const float*)d_in[2];
    const float* w_gate  = (const float*)d_in[3];
    const float* w_up    = (const float*)d_in[4];
    const float* w_down  = (const float*)d_in[5];
    const float* ws_gate = (const float*)d_in[6];
    const float* ws_up   = (const float*)d_in[7];
    const float* ws_down = (const float*)d_in[8];
    float* out = (float*)d_out;

    static bool attr_done = false;
    if (!attr_done) {
        cudaFuncSetAttribute(k_dual, cudaFuncAttributeMaxDynamicSharedMemorySize, SMEM_BYTES);
        cudaFuncSetAttribute(k_down, cudaFuncAttributeMaxDynamicSharedMemorySize, SMEM_BYTES);
        attr_done = true;
    }

    k_init<<<(T_TOK * H_DIM) / (256 * 4), 256>>>(out);
    k_xtf<<<(T_TOK * H_DIM) / (256 * 4), 256>>>(x);
    k_gate_route<<<T_TOK, 256>>>(x, gate_w, e_bias);
    // dual GEMMs: routed z=0..31, shared z=32..35
    k_dual<<<dim3(8, 8, E_NUM + 4), 128, SMEM_BYTES>>>(w_gate, w_up, ws_gate, ws_up);
    // down GEMMs: routed z=0..31, shared split-K z=32..35
    k_down<<<dim3(8, 8, E_NUM + 4), 128, SMEM_BYTES>>>(w_down, ws_down, out);
}